// round 2
// baseline (speedup 1.0000x reference)
#include <cuda_runtime.h>
#include <cuda_bf16.h>

// y = (x + 1) * 2/3 ; if y > 0 then y -= 5
// Pure HBM stream: float4, streaming cache hints (evict-first, zero reuse),
// single persistent wave, unroll-4 for front-batched LDGs.

__device__ __forceinline__ float f(float x) {
    const float c = 2.0f / 3.0f;
    float y = fmaf(x, c, c);        // (x+1)*2/3 == x*c + c
    return y > 0.0f ? y - 5.0f : y; // branchless
}

__device__ __forceinline__ float4 f4(float4 a) {
    return make_float4(f(a.x), f(a.y), f(a.z), f(a.w));
}

__global__ void __launch_bounds__(256) ew_kernel(const float4* __restrict__ in,
                                                 float4* __restrict__ out,
                                                 int n4) {
    int tid = blockIdx.x * blockDim.x + threadIdx.x;
    int stride = gridDim.x * blockDim.x;

    int i = tid;
    // unroll-4 grid-stride: 4 independent LDG.128 issued back-to-back
    for (; i + 3 * stride < n4; i += 4 * stride) {
        float4 a0 = __ldcs(in + i);
        float4 a1 = __ldcs(in + i + stride);
        float4 a2 = __ldcs(in + i + 2 * stride);
        float4 a3 = __ldcs(in + i + 3 * stride);
        __stcs(out + i,              f4(a0));
        __stcs(out + i + stride,     f4(a1));
        __stcs(out + i + 2 * stride, f4(a2));
        __stcs(out + i + 3 * stride, f4(a3));
    }
    for (; i < n4; i += stride) {
        __stcs(out + i, f4(__ldcs(in + i)));
    }
}

extern "C" void kernel_launch(void* const* d_in, const int* in_sizes, int n_in,
                              void* d_out, int out_size) {
    const float* x = (const float*)d_in[0];
    float* y = (float*)d_out;
    int n = in_sizes[0];          // 67108864, divisible by 4
    int n4 = n >> 2;              // 16M float4s

    const int threads = 256;
    // one fully-resident wave: 148 SMs x 8 CTAs (8 warps/CTA -> 64 warps/SM)
    int blocks = 148 * 8;         // 1184
    ew_kernel<<<blocks, threads>>>((const float4*)x, (float4*)y, n4);
}

// round 3
// speedup vs baseline: 1.1123x; 1.1123x over previous
#include <cuda_runtime.h>
#include <cuda_bf16.h>

// y = (x + 1) * 2/3 ; if y > 0 then y -= 5
// R3 = exact R1 structure (4736 blocks, unroll-2 grid-stride, float4)
//      + single change: streaming cache hints (__ldcs/__stcs).

__device__ __forceinline__ float f(float x) {
    const float c = 2.0f / 3.0f;
    float y = fmaf(x, c, c);        // (x+1)*2/3 == x*c + c
    return y > 0.0f ? y - 5.0f : y; // branchless
}

__global__ void __launch_bounds__(256) ew_kernel(const float4* __restrict__ in,
                                                 float4* __restrict__ out,
                                                 int n4) {
    int i = blockIdx.x * blockDim.x + threadIdx.x;
    int stride = gridDim.x * blockDim.x;
    for (; i + stride < n4; i += 2 * stride) {
        float4 a = __ldcs(in + i);
        float4 b = __ldcs(in + i + stride);
        float4 ra = make_float4(f(a.x), f(a.y), f(a.z), f(a.w));
        float4 rb = make_float4(f(b.x), f(b.y), f(b.z), f(b.w));
        __stcs(out + i, ra);
        __stcs(out + i + stride, rb);
    }
    if (i < n4) {
        float4 a = __ldcs(in + i);
        __stcs(out + i, make_float4(f(a.x), f(a.y), f(a.z), f(a.w)));
    }
}

extern "C" void kernel_launch(void* const* d_in, const int* in_sizes, int n_in,
                              void* d_out, int out_size) {
    const float* x = (const float*)d_in[0];
    float* y = (float*)d_out;
    int n = in_sizes[0];          // 67108864, divisible by 4
    int n4 = n >> 2;              // 16M float4s

    const int threads = 256;
    int blocks = 148 * 8 * 4;     // 4736 — R1's proven grid shape
    ew_kernel<<<blocks, threads>>>((const float4*)x, (float4*)y, n4);
}

// round 4
// speedup vs baseline: 1.1216x; 1.0084x over previous
#include <cuda_runtime.h>
#include <cuda_bf16.h>

// y = (x + 1) * 2/3 ; if y > 0 then y -= 5
// R4 = R1 grid shape (4736 x 256) + unroll-4 grid-stride (deeper MLP),
//      __launch_bounds__(256, 8) to hold 8 CTAs/SM despite higher reg count.

__device__ __forceinline__ float f(float x) {
    const float c = 2.0f / 3.0f;
    float y = fmaf(x, c, c);        // (x+1)*2/3 == x*c + c
    return y > 0.0f ? y - 5.0f : y; // branchless
}

__device__ __forceinline__ float4 f4(float4 a) {
    return make_float4(f(a.x), f(a.y), f(a.z), f(a.w));
}

__global__ void __launch_bounds__(256, 8) ew_kernel(const float4* __restrict__ in,
                                                    float4* __restrict__ out,
                                                    int n4) {
    int i = blockIdx.x * blockDim.x + threadIdx.x;
    int stride = gridDim.x * blockDim.x;

    // unroll-4: 4 independent LDG.128 front-batched per iteration
    for (; i + 3 * stride < n4; i += 4 * stride) {
        float4 a0 = in[i];
        float4 a1 = in[i + stride];
        float4 a2 = in[i + 2 * stride];
        float4 a3 = in[i + 3 * stride];
        out[i]              = f4(a0);
        out[i + stride]     = f4(a1);
        out[i + 2 * stride] = f4(a2);
        out[i + 3 * stride] = f4(a3);
    }
    for (; i < n4; i += stride) {
        out[i] = f4(in[i]);
    }
}

extern "C" void kernel_launch(void* const* d_in, const int* in_sizes, int n_in,
                              void* d_out, int out_size) {
    const float* x = (const float*)d_in[0];
    float* y = (float*)d_out;
    int n = in_sizes[0];          // 67108864, divisible by 4
    int n4 = n >> 2;              // 16M float4s

    const int threads = 256;
    int blocks = 148 * 8 * 4;     // 4736 — proven grid shape
    ew_kernel<<<blocks, threads>>>((const float4*)x, (float4*)y, n4);
}

// round 5
// speedup vs baseline: 1.1405x; 1.0168x over previous
#include <cuda_runtime.h>
#include <cuda_bf16.h>

// y = (x + 1) * 2/3 ; if y > 0 then y -= 5
// R5: loop-free exact-fit version. 67108864 floats = 16M float4.
// 16384 blocks x 256 threads = 4M threads, each handles exactly 4 float4s
// at stride 4M. No loop, no tail, minimal regs, 4 front-batched LDG.128.

__device__ __forceinline__ float f(float x) {
    const float c = 2.0f / 3.0f;
    float y = fmaf(x, c, c);        // (x+1)*2/3 == x*c + c
    return y > 0.0f ? y - 5.0f : y; // branchless
}

__device__ __forceinline__ float4 f4(float4 a) {
    return make_float4(f(a.x), f(a.y), f(a.z), f(a.w));
}

// Fast path: assumes n4 == 4 * gridDim.x * blockDim.x exactly.
__global__ void __launch_bounds__(256, 8) ew_exact(const float4* __restrict__ in,
                                                   float4* __restrict__ out) {
    int i = blockIdx.x * blockDim.x + threadIdx.x;
    const int S = gridDim.x * blockDim.x;   // 4194304
    float4 a0 = in[i];
    float4 a1 = in[i + S];
    float4 a2 = in[i + 2 * S];
    float4 a3 = in[i + 3 * S];
    out[i]         = f4(a0);
    out[i + S]     = f4(a1);
    out[i + 2 * S] = f4(a2);
    out[i + 3 * S] = f4(a3);
}

// Generic fallback (any size), same as R4.
__global__ void __launch_bounds__(256, 8) ew_generic(const float4* __restrict__ in,
                                                     float4* __restrict__ out,
                                                     int n4) {
    int i = blockIdx.x * blockDim.x + threadIdx.x;
    int stride = gridDim.x * blockDim.x;
    for (; i + 3 * stride < n4; i += 4 * stride) {
        float4 a0 = in[i];
        float4 a1 = in[i + stride];
        float4 a2 = in[i + 2 * stride];
        float4 a3 = in[i + 3 * stride];
        out[i]              = f4(a0);
        out[i + stride]     = f4(a1);
        out[i + 2 * stride] = f4(a2);
        out[i + 3 * stride] = f4(a3);
    }
    for (; i < n4; i += stride) {
        out[i] = f4(in[i]);
    }
}

extern "C" void kernel_launch(void* const* d_in, const int* in_sizes, int n_in,
                              void* d_out, int out_size) {
    const float* x = (const float*)d_in[0];
    float* y = (float*)d_out;
    int n = in_sizes[0];          // 67108864
    const int threads = 256;

    if ((n & 3) == 0) {
        int n4 = n >> 2;          // 16777216
        // each thread: exactly 4 float4 -> need n4/4 threads
        if ((n4 & (4 * threads - 1)) == 0) {
            int blocks = n4 / (4 * threads);   // 16384
            ew_exact<<<blocks, threads>>>((const float4*)x, (float4*)y);
            return;
        }
        ew_generic<<<148 * 8 * 4, threads>>>((const float4*)x, (float4*)y, n4);
        return;
    }
    // (unreachable for this problem's shape; kept for safety)
    ew_generic<<<148 * 8 * 4, threads>>>((const float4*)x, (float4*)y, n / 4);
}